// round 1
// baseline (speedup 1.0000x reference)
#include <cuda_runtime.h>
#include <cuda_fp16.h>
#include <mma.h>

using namespace nvcuda;

// Problem constants
#define BATCH 512
#define SEQ   256
#define EMB   384
#define EMB3  1152
#define MTOT  (BATCH * SEQ)        // 131072
#define QT_ROWS 64                 // q rows per attention CTA

// Scratch (allocation-free: __device__ globals)
__device__ __align__(16) half g_qkv[(size_t)MTOT * EMB3];   // [M,1152] fp16: q|k|v
__device__ __align__(16) half g_att[(size_t)MTOT * EMB];    // [M,384]  fp16 attention out

// ---------------------------------------------------------------------------
// Kernel 1: QKV GEMM  qkv = x @ W_qkv + b_qkv   (fp32 in -> fp16 out, fp32 acc)
// CTA tile 128x128, K-chunk 32, 8 warps each 32x64 (2x4 wmma frags)
// ---------------------------------------------------------------------------
__global__ __launch_bounds__(256) void qkv_gemm_kernel(
    const float* __restrict__ x, const float* __restrict__ Wqkv,
    const float* __restrict__ bqkv)
{
    __shared__ half As[128][48];    // ld 48 halfs (96B, mult of 16B)
    __shared__ half Bs[32][136];    // ld 136 halfs
    __shared__ float stage[8][16][16];

    const int tid  = threadIdx.x;
    const int warp = tid >> 5, lane = tid & 31;
    const int m0 = blockIdx.y * 128, n0 = blockIdx.x * 128;
    const int wr = warp >> 1, wc = warp & 1;   // 4 row-blocks x 2 col-blocks

    wmma::fragment<wmma::accumulator, 16, 16, 16, float> acc[2][4];
#pragma unroll
    for (int i = 0; i < 2; i++)
#pragma unroll
        for (int j = 0; j < 4; j++) wmma::fill_fragment(acc[i][j], 0.0f);

    for (int k0 = 0; k0 < EMB; k0 += 32) {
        // load A tile: x [128 x 32] fp32 -> half
#pragma unroll
        for (int i = 0; i < 4; i++) {
            int idx = tid + i * 256;
            int row = idx >> 3, c4 = (idx & 7) * 4;
            float4 v = *(const float4*)(x + (size_t)(m0 + row) * EMB + k0 + c4);
            As[row][c4 + 0] = __float2half_rn(v.x);
            As[row][c4 + 1] = __float2half_rn(v.y);
            As[row][c4 + 2] = __float2half_rn(v.z);
            As[row][c4 + 3] = __float2half_rn(v.w);
        }
        // load B tile: Wqkv [32 x 128] fp32 -> half
#pragma unroll
        for (int i = 0; i < 4; i++) {
            int idx = tid + i * 256;
            int row = idx >> 5, c4 = (idx & 31) * 4;
            float4 v = *(const float4*)(Wqkv + (size_t)(k0 + row) * EMB3 + n0 + c4);
            Bs[row][c4 + 0] = __float2half_rn(v.x);
            Bs[row][c4 + 1] = __float2half_rn(v.y);
            Bs[row][c4 + 2] = __float2half_rn(v.z);
            Bs[row][c4 + 3] = __float2half_rn(v.w);
        }
        __syncthreads();
#pragma unroll
        for (int kk = 0; kk < 32; kk += 16) {
            wmma::fragment<wmma::matrix_a, 16, 16, 16, half, wmma::row_major> af[2];
            wmma::fragment<wmma::matrix_b, 16, 16, 16, half, wmma::row_major> bf[4];
#pragma unroll
            for (int i = 0; i < 2; i++)
                wmma::load_matrix_sync(af[i], &As[wr * 32 + i * 16][kk], 48);
#pragma unroll
            for (int j = 0; j < 4; j++)
                wmma::load_matrix_sync(bf[j], &Bs[kk][wc * 64 + j * 16], 136);
#pragma unroll
            for (int i = 0; i < 2; i++)
#pragma unroll
                for (int j = 0; j < 4; j++)
                    wmma::mma_sync(acc[i][j], af[i], bf[j], acc[i][j]);
        }
        __syncthreads();
    }

    // epilogue: bias add, fp16 store
#pragma unroll
    for (int i = 0; i < 2; i++)
#pragma unroll
        for (int j = 0; j < 4; j++) {
            wmma::store_matrix_sync(&stage[warp][0][0], acc[i][j], 16, wmma::mem_row_major);
            __syncwarp();
            int grow0 = m0 + wr * 32 + i * 16;
            int gcol0 = n0 + wc * 64 + j * 16;
#pragma unroll
            for (int e = 0; e < 8; e++) {
                int idx = lane * 8 + e;
                int r = idx >> 4, c = idx & 15;
                g_qkv[(size_t)(grow0 + r) * EMB3 + gcol0 + c] =
                    __float2half_rn(stage[warp][r][c] + bqkv[gcol0 + c]);
            }
            __syncwarp();
        }
}

// ---------------------------------------------------------------------------
// Kernel 2: causal attention, one CTA per (batch, 64-row q-tile).
// Full S row in smem (fp32), then softmax, then P@V with fp32 acc.
// smem: QS half[64][392] | KS half[64][392] | SS f32[64][256] | PS half[64][256]
// ---------------------------------------------------------------------------
#define SM_QS 0
#define SM_KS 50176
#define SM_SS 100352
#define SM_PS 165888
#define SMEM_ATTN 198656

__global__ __launch_bounds__(256) void attn_kernel()
{
    extern __shared__ unsigned char smem_raw[];
    half*  QS = (half*)(smem_raw + SM_QS);    // ld 392
    half*  KS = (half*)(smem_raw + SM_KS);    // ld 392 (reused for V)
    float* SS = (float*)(smem_raw + SM_SS);   // ld 256
    half*  PS = (half*)(smem_raw + SM_PS);    // ld 256

    const int tid  = threadIdx.x;
    const int warp = tid >> 5, lane = tid & 31;
    const int b  = blockIdx.x >> 2;
    const int qt = blockIdx.x & 3;
    const int t0 = qt * QT_ROWS;
    const int nst = qt + 1;          // causal: only key tiles 0..qt
    const int send = nst * 64;

    // load Q tile [64 x 384] fp16 (vectorized uint4 = 8 halfs)
    {
        const half* qbase = g_qkv + (size_t)(b * SEQ + t0) * EMB3;
        for (int idx = tid; idx < 64 * 48; idx += 256) {
            int row = idx / 48, c8 = (idx % 48) * 8;
            *(uint4*)&QS[row * 392 + c8] = *(const uint4*)&qbase[row * EMB3 + c8];
        }
    }

    // ---- S = Q K^T, tile by tile ----
    for (int st = 0; st < nst; st++) {
        int s0 = st * 64;
        const half* kbase = g_qkv + (size_t)(b * SEQ + s0) * EMB3 + EMB;
        for (int idx = tid; idx < 64 * 48; idx += 256) {
            int row = idx / 48, c8 = (idx % 48) * 8;
            *(uint4*)&KS[row * 392 + c8] = *(const uint4*)&kbase[row * EMB3 + c8];
        }
        __syncthreads();

        // 8 warps: 2 row-blocks (32) x 4 col-blocks (16)
        const int wr = warp >> 2, wc = warp & 3;
        wmma::fragment<wmma::accumulator, 16, 16, 16, float> sacc[2];
#pragma unroll
        for (int i = 0; i < 2; i++) wmma::fill_fragment(sacc[i], 0.0f);
#pragma unroll
        for (int k = 0; k < EMB; k += 16) {
            wmma::fragment<wmma::matrix_a, 16, 16, 16, half, wmma::row_major> af;
            wmma::fragment<wmma::matrix_b, 16, 16, 16, half, wmma::col_major> bf;
            wmma::load_matrix_sync(bf, KS + (wc * 16) * 392 + k, 392);
#pragma unroll
            for (int i = 0; i < 2; i++) {
                wmma::load_matrix_sync(af, QS + (wr * 32 + i * 16) * 392 + k, 392);
                wmma::mma_sync(sacc[i], af, bf, sacc[i]);
            }
        }
#pragma unroll
        for (int i = 0; i < 2; i++)
            wmma::store_matrix_sync(SS + (wr * 32 + i * 16) * 256 + s0 + wc * 16,
                                    sacc[i], 256, wmma::mem_row_major);
        __syncthreads();
    }

    // ---- softmax (fp32), causal mask, write P fp16 ----
    {
        const float inv_sqrt = 0.05103103630798288f;   // 1/sqrt(384)
        for (int r = warp * 8; r < warp * 8 + 8; r++) {
            int tglob = t0 + r;
            float* srow = SS + r * 256;
            float mx = -1e30f;
            for (int c = lane; c < send; c += 32) {
                float v = srow[c] * inv_sqrt;
                if (c > tglob) v = -1e30f;
                srow[c] = v;
                mx = fmaxf(mx, v);
            }
#pragma unroll
            for (int o = 16; o > 0; o >>= 1)
                mx = fmaxf(mx, __shfl_xor_sync(0xffffffffu, mx, o));
            float sum = 0.f;
            for (int c = lane; c < send; c += 32) {
                float e = __expf(srow[c] - mx);
                srow[c] = e;
                sum += e;
            }
#pragma unroll
            for (int o = 16; o > 0; o >>= 1)
                sum += __shfl_xor_sync(0xffffffffu, sum, o);
            float rs = 1.0f / sum;
            for (int c = lane; c < send; c += 32)
                PS[r * 256 + c] = __float2half_rn(srow[c] * rs);
        }
    }
    __syncthreads();

    // ---- O = P @ V, fp32 acc in regs ----
    {
        const int wr = warp >> 1, wc = warp & 1;   // 4 row-blocks(16) x 2 col-blocks(192)
        wmma::fragment<wmma::accumulator, 16, 16, 16, float> o[12];
#pragma unroll
        for (int j = 0; j < 12; j++) wmma::fill_fragment(o[j], 0.0f);

        for (int st = 0; st < nst; st++) {
            int s0 = st * 64;
            __syncthreads();   // previous V-tile consumers done
            const half* vbase = g_qkv + (size_t)(b * SEQ + s0) * EMB3 + 2 * EMB;
            for (int idx = tid; idx < 64 * 48; idx += 256) {
                int row = idx / 48, c8 = (idx % 48) * 8;
                *(uint4*)&KS[row * 392 + c8] = *(const uint4*)&vbase[row * EMB3 + c8];
            }
            __syncthreads();
#pragma unroll
            for (int ks = 0; ks < 4; ks++) {
                wmma::fragment<wmma::matrix_a, 16, 16, 16, half, wmma::row_major> af;
                wmma::load_matrix_sync(af, PS + (wr * 16) * 256 + s0 + ks * 16, 256);
#pragma unroll
                for (int j = 0; j < 12; j++) {
                    wmma::fragment<wmma::matrix_b, 16, 16, 16, half, wmma::row_major> bf;
                    wmma::load_matrix_sync(bf, KS + (ks * 16) * 392 + wc * 192 + j * 16, 392);
                    wmma::mma_sync(o[j], af, bf, o[j]);
                }
            }
        }
        __syncthreads();
        // stage O in smem (reuse QS+KS region as fp32 [64][384])
        float* OS = (float*)smem_raw;
#pragma unroll
        for (int j = 0; j < 12; j++)
            wmma::store_matrix_sync(OS + (wr * 16) * 384 + wc * 192 + j * 16,
                                    o[j], 384, wmma::mem_row_major);
        __syncthreads();
        half* obase = g_att + (size_t)(b * SEQ + t0) * EMB;
        for (int idx = tid; idx < 64 * 192; idx += 256) {
            int row = idx / 192, c2 = (idx % 192) * 2;
            float2 v = *(float2*)&((float*)smem_raw)[row * 384 + c2];
            *(half2*)&obase[row * EMB + c2] = __floats2half2_rn(v.x, v.y);
        }
    }
}

// ---------------------------------------------------------------------------
// Kernel 3: out = att @ W_proj + b_proj  (fp16 A, fp32 W->fp16, fp32 out)
// ---------------------------------------------------------------------------
__global__ __launch_bounds__(256) void proj_gemm_kernel(
    const float* __restrict__ Wproj, const float* __restrict__ bproj,
    float* __restrict__ out)
{
    __shared__ half As[128][48];
    __shared__ half Bs[32][136];
    __shared__ float stage[8][16][16];

    const int tid  = threadIdx.x;
    const int warp = tid >> 5, lane = tid & 31;
    const int m0 = blockIdx.y * 128, n0 = blockIdx.x * 128;
    const int wr = warp >> 1, wc = warp & 1;

    wmma::fragment<wmma::accumulator, 16, 16, 16, float> acc[2][4];
#pragma unroll
    for (int i = 0; i < 2; i++)
#pragma unroll
        for (int j = 0; j < 4; j++) wmma::fill_fragment(acc[i][j], 0.0f);

    for (int k0 = 0; k0 < EMB; k0 += 32) {
        // A tile from g_att (already fp16): 128 x 32
#pragma unroll
        for (int i = 0; i < 2; i++) {
            int idx = tid + i * 256;
            int row = idx >> 2, c8 = (idx & 3) * 8;
            *(uint4*)&As[row][c8] =
                *(const uint4*)(g_att + (size_t)(m0 + row) * EMB + k0 + c8);
        }
        // B tile from W_proj fp32: 32 x 128
#pragma unroll
        for (int i = 0; i < 4; i++) {
            int idx = tid + i * 256;
            int row = idx >> 5, c4 = (idx & 31) * 4;
            float4 v = *(const float4*)(Wproj + (size_t)(k0 + row) * EMB + n0 + c4);
            Bs[row][c4 + 0] = __float2half_rn(v.x);
            Bs[row][c4 + 1] = __float2half_rn(v.y);
            Bs[row][c4 + 2] = __float2half_rn(v.z);
            Bs[row][c4 + 3] = __float2half_rn(v.w);
        }
        __syncthreads();
#pragma unroll
        for (int kk = 0; kk < 32; kk += 16) {
            wmma::fragment<wmma::matrix_a, 16, 16, 16, half, wmma::row_major> af[2];
            wmma::fragment<wmma::matrix_b, 16, 16, 16, half, wmma::row_major> bf[4];
#pragma unroll
            for (int i = 0; i < 2; i++)
                wmma::load_matrix_sync(af[i], &As[wr * 32 + i * 16][kk], 48);
#pragma unroll
            for (int j = 0; j < 4; j++)
                wmma::load_matrix_sync(bf[j], &Bs[kk][wc * 64 + j * 16], 136);
#pragma unroll
            for (int i = 0; i < 2; i++)
#pragma unroll
                for (int j = 0; j < 4; j++)
                    wmma::mma_sync(acc[i][j], af[i], bf[j], acc[i][j]);
        }
        __syncthreads();
    }

#pragma unroll
    for (int i = 0; i < 2; i++)
#pragma unroll
        for (int j = 0; j < 4; j++) {
            wmma::store_matrix_sync(&stage[warp][0][0], acc[i][j], 16, wmma::mem_row_major);
            __syncwarp();
            int grow0 = m0 + wr * 32 + i * 16;
            int gcol0 = n0 + wc * 64 + j * 16;
#pragma unroll
            for (int e = 0; e < 8; e++) {
                int idx = lane * 8 + e;
                int r = idx >> 4, c = idx & 15;
                out[(size_t)(grow0 + r) * EMB + gcol0 + c] =
                    stage[warp][r][c] + bproj[gcol0 + c];
            }
            __syncwarp();
        }
}

// ---------------------------------------------------------------------------
extern "C" void kernel_launch(void* const* d_in, const int* in_sizes, int n_in,
                              void* d_out, int out_size)
{
    const float* x     = (const float*)d_in[0];
    const float* Wqkv  = (const float*)d_in[1];
    const float* bqkv  = (const float*)d_in[2];
    const float* Wproj = (const float*)d_in[3];
    const float* bproj = (const float*)d_in[4];
    float* out = (float*)d_out;

    cudaFuncSetAttribute(attn_kernel, cudaFuncAttributeMaxDynamicSharedMemorySize,
                         SMEM_ATTN);

    qkv_gemm_kernel<<<dim3(EMB3 / 128, MTOT / 128), 256>>>(x, Wqkv, bqkv);
    attn_kernel<<<BATCH * (SEQ / QT_ROWS), 256, SMEM_ATTN>>>();
    proj_gemm_kernel<<<dim3(EMB / 128, MTOT / 128), 256>>>(Wproj, bproj, out);
}

// round 3
// speedup vs baseline: 1.9109x; 1.9109x over previous
#include <cuda_runtime.h>
#include <cuda_fp16.h>
#include <mma.h>

using namespace nvcuda;

#define BATCH 512
#define SEQ   256
#define EMB   384
#define EMB3  1152
#define MTOT  (BATCH * SEQ)        // 131072
#define QT_ROWS 64

// Scratch (__device__ globals — allocation-free)
__device__ __align__(16) half g_xh [(size_t)MTOT * EMB];    // x in fp16
__device__ __align__(16) half g_wqkv[(size_t)EMB * EMB3];   // W_qkv fp16
__device__ __align__(16) half g_wproj[(size_t)EMB * EMB];   // W_proj fp16
__device__ __align__(16) half g_qkv[(size_t)MTOT * EMB3];   // q|k|v fp16
__device__ __align__(16) half g_att[(size_t)MTOT * EMB];    // attention out fp16

// ---------------------------------------------------------------------------
// cp.async helpers
// ---------------------------------------------------------------------------
__device__ __forceinline__ void cp16(void* smem, const void* gmem) {
    unsigned s = (unsigned)__cvta_generic_to_shared(smem);
    asm volatile("cp.async.cg.shared.global [%0], [%1], 16;\n" :: "r"(s), "l"(gmem));
}
__device__ __forceinline__ void cp_commit() {
    asm volatile("cp.async.commit_group;\n");
}
template<int N> __device__ __forceinline__ void cp_wait() {
    asm volatile("cp.async.wait_group %0;\n" :: "n"(N));
}

// ---------------------------------------------------------------------------
// fp32 -> fp16 conversion (vectorized)
// ---------------------------------------------------------------------------
struct h4 { half2 a, b; };
__global__ __launch_bounds__(256) void f2h_kernel(const float* __restrict__ src,
                                                  half* __restrict__ dst, int n4) {
    int i = blockIdx.x * 256 + threadIdx.x;
    if (i < n4) {
        float4 v = ((const float4*)src)[i];
        h4 o;
        o.a = __floats2half2_rn(v.x, v.y);
        o.b = __floats2half2_rn(v.z, v.w);
        ((h4*)dst)[i] = o;
    }
}

// ---------------------------------------------------------------------------
// Pipelined GEMM: C[M, N] = A[M,384] @ B[384,N] + bias, 2-stage cp.async
// BM=128 BN=128 BK=64, 8 warps x (32x64), fp16 in, fp32 acc
// smem: As[2][128][72]h, Bs[2][64][136]h  (71680 B), epilogue reuses as fp32
// ---------------------------------------------------------------------------
#define GS_AS0 0
#define GS_AS1 18432
#define GS_BS0 36864
#define GS_BS1 54272
#define GEMM_SMEM 71680

template<int NCOLS, bool HALF_OUT>
__global__ __launch_bounds__(256) void gemm_kernel(
    const half* __restrict__ A, const half* __restrict__ B,
    const float* __restrict__ bias, void* __restrict__ Cout)
{
    extern __shared__ unsigned char smem[];
    half* AS[2] = { (half*)(smem + GS_AS0), (half*)(smem + GS_AS1) };
    half* BS[2] = { (half*)(smem + GS_BS0), (half*)(smem + GS_BS1) };

    const int tid  = threadIdx.x;
    const int warp = tid >> 5, lane = tid & 31;
    const int m0 = blockIdx.y * 128, n0 = blockIdx.x * 128;
    const int wr = warp >> 1, wc = warp & 1;

    wmma::fragment<wmma::accumulator, 16, 16, 16, float> acc[2][4];
#pragma unroll
    for (int i = 0; i < 2; i++)
#pragma unroll
        for (int j = 0; j < 4; j++) wmma::fill_fragment(acc[i][j], 0.0f);

    auto load_chunk = [&](int k0, int s) {
        // A: 128x64 halfs = 1024 x 16B
#pragma unroll
        for (int i = 0; i < 4; i++) {
            int o = tid + i * 256;
            int row = o >> 3, c = o & 7;
            cp16(AS[s] + row * 72 + c * 8,
                 A + (size_t)(m0 + row) * EMB + k0 + c * 8);
        }
        // B: 64x128 halfs = 1024 x 16B
#pragma unroll
        for (int i = 0; i < 4; i++) {
            int o = tid + i * 256;
            int row = o >> 4, c = o & 15;
            cp16(BS[s] + row * 136 + c * 8,
                 B + (size_t)(k0 + row) * NCOLS + n0 + c * 8);
        }
        cp_commit();
    };

    load_chunk(0, 0);
    const int KC = EMB / 64;  // 6
#pragma unroll 1
    for (int kc = 0; kc < KC; kc++) {
        if (kc + 1 < KC) load_chunk((kc + 1) * 64, (kc + 1) & 1);
        if (kc + 1 < KC) cp_wait<1>(); else cp_wait<0>();
        __syncthreads();
        const half* as = AS[kc & 1];
        const half* bs = BS[kc & 1];
#pragma unroll
        for (int kk = 0; kk < 64; kk += 16) {
            wmma::fragment<wmma::matrix_a, 16, 16, 16, half, wmma::row_major> af[2];
            wmma::fragment<wmma::matrix_b, 16, 16, 16, half, wmma::row_major> bf[4];
#pragma unroll
            for (int i = 0; i < 2; i++)
                wmma::load_matrix_sync(af[i], as + (wr * 32 + i * 16) * 72 + kk, 72);
#pragma unroll
            for (int j = 0; j < 4; j++)
                wmma::load_matrix_sync(bf[j], bs + kk * 136 + wc * 64 + j * 16, 136);
#pragma unroll
            for (int i = 0; i < 2; i++)
#pragma unroll
                for (int j = 0; j < 4; j++)
                    wmma::mma_sync(acc[i][j], af[i], bf[j], acc[i][j]);
        }
        __syncthreads();
    }

    // Epilogue: per-warp fp32 stage [32][68] (aligned float4 rows), then
    // vectorized bias+convert+store.
    float* st = (float*)(smem + warp * 8704);
#pragma unroll
    for (int i = 0; i < 2; i++)
#pragma unroll
        for (int j = 0; j < 4; j++)
            wmma::store_matrix_sync(st + (i * 16) * 68 + j * 16, acc[i][j], 68,
                                    wmma::mem_row_major);
    const int rowbase = m0 + wr * 32;
    const int colbase = n0 + wc * 64;
#pragma unroll
    for (int e = 0; e < 16; e++) {
        int ci = e * 32 + lane;
        int r = ci >> 4, c4 = (ci & 15) << 2;
        float4 v = *(const float4*)(st + r * 68 + c4);
        float4 b4 = *(const float4*)(bias + colbase + c4);
        v.x += b4.x; v.y += b4.y; v.z += b4.z; v.w += b4.w;
        if (HALF_OUT) {
            h4 o;
            o.a = __floats2half2_rn(v.x, v.y);
            o.b = __floats2half2_rn(v.z, v.w);
            *(h4*)((half*)Cout + (size_t)(rowbase + r) * NCOLS + colbase + c4) = o;
        } else {
            *(float4*)((float*)Cout + (size_t)(rowbase + r) * NCOLS + colbase + c4) = v;
        }
    }
}

// ---------------------------------------------------------------------------
// Attention: one CTA per (batch, 64-row q tile). 32-row K/V subtiles,
// double-buffered cp.async; full-row S fp32 softmax; P@V fp32 accum.
// smem: QS h[64][392] | KV h[2][32][392] | SS f32[64][256] | PS h[64][256]
// ---------------------------------------------------------------------------
#define SM_QS 0
#define SM_KV0 50176
#define SM_KV1 75264
#define SM_SS 100352
#define SM_PS 165888
#define SMEM_ATTN 198656

__global__ __launch_bounds__(256) void attn_kernel()
{
    extern __shared__ unsigned char smem[];
    half*  QS = (half*)(smem + SM_QS);
    half*  KV[2] = { (half*)(smem + SM_KV0), (half*)(smem + SM_KV1) };
    float* SS = (float*)(smem + SM_SS);
    half*  PS = (half*)(smem + SM_PS);

    const int tid  = threadIdx.x;
    const int warp = tid >> 5, lane = tid & 31;
    const int b  = blockIdx.x >> 2;
    const int qt = blockIdx.x & 3;
    const int t0 = qt * QT_ROWS;
    const int nst = qt + 1;
    const int NS = nst * 2;          // 32-row subtiles
    const int send = nst * 64;

    auto load_kv = [&](int sub, int buf, int qkv_off) {
        const half* base = g_qkv + (size_t)(b * SEQ + sub * 32) * EMB3 + qkv_off;
#pragma unroll
        for (int i = 0; i < 6; i++) {
            int o = tid + i * 256;
            int row = o / 48, c = o % 48;
            cp16(KV[buf] + row * 392 + c * 8, base + (size_t)row * EMB3 + c * 8);
        }
        cp_commit();
    };

    // Prefetch Q + K0 as group 0, K1 as group 1
    {
        const half* qbase = g_qkv + (size_t)(b * SEQ + t0) * EMB3;
#pragma unroll
        for (int i = 0; i < 12; i++) {
            int o = tid + i * 256;
            int row = o / 48, c = o % 48;
            cp16(QS + row * 392 + c * 8, qbase + (size_t)row * EMB3 + c * 8);
        }
        load_kv(0, 0, EMB);   // commits Q+K0 together
    }

    // ---- S = Q K^T ----
    const int wrS = warp >> 1, wcS = warp & 1;   // 4 row blocks x 2 col blocks
#pragma unroll 1
    for (int ss = 0; ss < NS; ss++) {
        if (ss + 1 < NS) load_kv(ss + 1, (ss + 1) & 1, EMB);
        if (ss + 1 < NS) cp_wait<1>(); else cp_wait<0>();
        __syncthreads();
        const half* ks = KV[ss & 1];

        wmma::fragment<wmma::accumulator, 16, 16, 16, float> s0, s1;
        wmma::fill_fragment(s0, 0.0f);
        wmma::fill_fragment(s1, 0.0f);
#pragma unroll
        for (int k = 0; k < EMB; k += 32) {
            wmma::fragment<wmma::matrix_a, 16, 16, 16, half, wmma::row_major> a0, a1;
            wmma::fragment<wmma::matrix_b, 16, 16, 16, half, wmma::col_major> b0, b1;
            wmma::load_matrix_sync(a0, QS + (wrS * 16) * 392 + k, 392);
            wmma::load_matrix_sync(b0, ks + (wcS * 16) * 392 + k, 392);
            wmma::load_matrix_sync(a1, QS + (wrS * 16) * 392 + k + 16, 392);
            wmma::load_matrix_sync(b1, ks + (wcS * 16) * 392 + k + 16, 392);
            wmma::mma_sync(s0, a0, b0, s0);
            wmma::mma_sync(s1, a1, b1, s1);
        }
#pragma unroll
        for (int e = 0; e < s0.num_elements; e++) s0.x[e] += s1.x[e];
        wmma::store_matrix_sync(SS + (wrS * 16) * 256 + ss * 32 + wcS * 16, s0, 256,
                                wmma::mem_row_major);
        __syncthreads();
    }

    // Prefetch V0 (buffers free after S phase's trailing sync), overlap softmax
    load_kv(0, 0, 2 * EMB);

    // ---- softmax (fp32) ----
    {
        const float inv_sqrt = 0.05103103630798288f;   // 1/sqrt(384)
        for (int r = warp * 8; r < warp * 8 + 8; r++) {
            int tglob = t0 + r;
            float* srow = SS + r * 256;
            float mx = -1e30f;
            for (int c = lane; c < send; c += 32) {
                float v = srow[c] * inv_sqrt;
                if (c > tglob) v = -1e30f;
                srow[c] = v;
                mx = fmaxf(mx, v);
            }
#pragma unroll
            for (int o = 16; o > 0; o >>= 1)
                mx = fmaxf(mx, __shfl_xor_sync(0xffffffffu, mx, o));
            float sum = 0.f;
            for (int c = lane; c < send; c += 32) {
                float e = __expf(srow[c] - mx);
                srow[c] = e;
                sum += e;
            }
#pragma unroll
            for (int o = 16; o > 0; o >>= 1)
                sum += __shfl_xor_sync(0xffffffffu, sum, o);
            float rs = 1.0f / sum;
            for (int c = lane; c < send; c += 32)
                PS[r * 256 + c] = __float2half_rn(srow[c] * rs);
        }
    }

    // ---- O = P @ V ----
    {
        const int wr = warp >> 1, wc = warp & 1;   // 4 x 16 rows, 2 x 192 cols
        wmma::fragment<wmma::accumulator, 16, 16, 16, float> o[12];
#pragma unroll
        for (int j = 0; j < 12; j++) wmma::fill_fragment(o[j], 0.0f);

#pragma unroll 1
        for (int sv = 0; sv < NS; sv++) {
            if (sv + 1 < NS) load_kv(sv + 1, (sv + 1) & 1, 2 * EMB);
            if (sv + 1 < NS) cp_wait<1>(); else cp_wait<0>();
            __syncthreads();
            const half* vs = KV[sv & 1];
#pragma unroll
            for (int kk = 0; kk < 2; kk++) {
                wmma::fragment<wmma::matrix_a, 16, 16, 16, half, wmma::row_major> af;
                wmma::load_matrix_sync(af, PS + (wr * 16) * 256 + sv * 32 + kk * 16, 256);
#pragma unroll
                for (int j = 0; j < 12; j++) {
                    wmma::fragment<wmma::matrix_b, 16, 16, 16, half, wmma::row_major> bf;
                    wmma::load_matrix_sync(bf, vs + (kk * 16) * 392 + wc * 192 + j * 16, 392);
                    wmma::mma_sync(o[j], af, bf, o[j]);
                }
            }
            __syncthreads();
        }

        // stage O fp32 in smem (reuse QS+KV region: 64x384 f32 = 96KB)
        float* OS = (float*)smem;
#pragma unroll
        for (int j = 0; j < 12; j++)
            wmma::store_matrix_sync(OS + (wr * 16) * 384 + wc * 192 + j * 16, o[j],
                                    384, wmma::mem_row_major);
        __syncthreads();
        half* obase = g_att + (size_t)(b * SEQ + t0) * EMB;
#pragma unroll
        for (int i = 0; i < 24; i++) {
            int oi = tid + i * 256;
            int row = oi / 96, c4 = (oi % 96) * 4;
            float4 v = *(const float4*)(OS + row * 384 + c4);
            h4 h;
            h.a = __floats2half2_rn(v.x, v.y);
            h.b = __floats2half2_rn(v.z, v.w);
            *(h4*)(obase + (size_t)row * EMB + c4) = h;
        }
    }
}

// ---------------------------------------------------------------------------
extern "C" void kernel_launch(void* const* d_in, const int* in_sizes, int n_in,
                              void* d_out, int out_size)
{
    const float* x     = (const float*)d_in[0];
    const float* Wqkv  = (const float*)d_in[1];
    const float* bqkv  = (const float*)d_in[2];
    const float* Wproj = (const float*)d_in[3];
    const float* bproj = (const float*)d_in[4];
    float* out = (float*)d_out;

    half *xh, *wqkvh, *wprojh;
    cudaGetSymbolAddress((void**)&xh, g_xh);
    cudaGetSymbolAddress((void**)&wqkvh, g_wqkv);
    cudaGetSymbolAddress((void**)&wprojh, g_wproj);

    cudaFuncSetAttribute(attn_kernel, cudaFuncAttributeMaxDynamicSharedMemorySize,
                         SMEM_ATTN);
    cudaFuncSetAttribute(gemm_kernel<EMB3, true>,
                         cudaFuncAttributeMaxDynamicSharedMemorySize, GEMM_SMEM);
    cudaFuncSetAttribute(gemm_kernel<EMB, false>,
                         cudaFuncAttributeMaxDynamicSharedMemorySize, GEMM_SMEM);

    // fp32 -> fp16 conversions
    {
        int n4x = MTOT * EMB / 4;                // 12582912
        f2h_kernel<<<(n4x + 255) / 256, 256>>>(x, xh, n4x);
        int n4q = EMB * EMB3 / 4;                // 110592
        f2h_kernel<<<(n4q + 255) / 256, 256>>>(Wqkv, wqkvh, n4q);
        int n4p = EMB * EMB / 4;                 // 36864
        f2h_kernel<<<(n4p + 255) / 256, 256>>>(Wproj, wprojh, n4p);
    }

    half *qkv_ptr, *att_ptr;
    cudaGetSymbolAddress((void**)&qkv_ptr, g_qkv);
    cudaGetSymbolAddress((void**)&att_ptr, g_att);

    gemm_kernel<EMB3, true><<<dim3(EMB3 / 128, MTOT / 128), 256, GEMM_SMEM>>>(
        xh, wqkvh, bqkv, qkv_ptr);
    attn_kernel<<<BATCH * (SEQ / QT_ROWS), 256, SMEM_ATTN>>>();
    gemm_kernel<EMB, false><<<dim3(EMB / 128, MTOT / 128), 256, GEMM_SMEM>>>(
        att_ptr, wprojh, bproj, out);
}

// round 8
// speedup vs baseline: 2.2837x; 1.1951x over previous
#include <cuda_runtime.h>
#include <cuda_fp16.h>
#include <mma.h>

using namespace nvcuda;

#define BATCH 512
#define SEQ   256
#define EMB   384
#define EMB3  1152
#define MTOT  (BATCH * SEQ)        // 131072
#define QT_ROWS 64

// Scratch (__device__ globals — allocation-free)
__device__ __align__(16) half g_xh [(size_t)MTOT * EMB];    // x in fp16
__device__ __align__(16) half g_wqkv[(size_t)EMB * EMB3];   // W_qkv fp16
__device__ __align__(16) half g_wproj[(size_t)EMB * EMB];   // W_proj fp16
__device__ __align__(16) half g_qkv[(size_t)MTOT * EMB3];   // q|k|v fp16
__device__ __align__(16) half g_att[(size_t)MTOT * EMB];    // attention out fp16

// ---------------------------------------------------------------------------
// cp.async helpers
// ---------------------------------------------------------------------------
__device__ __forceinline__ void cp16(void* smem, const void* gmem) {
    unsigned s = (unsigned)__cvta_generic_to_shared(smem);
    asm volatile("cp.async.cg.shared.global [%0], [%1], 16;\n" :: "r"(s), "l"(gmem));
}
__device__ __forceinline__ void cp_commit() {
    asm volatile("cp.async.commit_group;\n");
}
template<int N> __device__ __forceinline__ void cp_wait() {
    asm volatile("cp.async.wait_group %0;\n" :: "n"(N));
}

// ---------------------------------------------------------------------------
// fp32 -> fp16 conversion (vectorized)
// ---------------------------------------------------------------------------
struct h4 { half2 a, b; };
__global__ __launch_bounds__(256) void f2h_kernel(const float* __restrict__ src,
                                                  half* __restrict__ dst, int n4) {
    int i = blockIdx.x * 256 + threadIdx.x;
    if (i < n4) {
        float4 v = ((const float4*)src)[i];
        h4 o;
        o.a = __floats2half2_rn(v.x, v.y);
        o.b = __floats2half2_rn(v.z, v.w);
        ((h4*)dst)[i] = o;
    }
}

// ---------------------------------------------------------------------------
// Pipelined GEMM: C[M, N] = A[M,384] @ B[384,N] + bias, 3-stage cp.async
// BM=128 BN=128 BK=64, 8 warps x (32x64), fp16 in, fp32 acc.
// One __syncthreads per K-chunk; prefetch distance 2.
// smem per stage: As 128x72 h (18432B) + Bs 64x136 h (17408B) = 35840B
// 3 stages = 107520B; epilogue reuses as per-warp fp32 stage.
// ---------------------------------------------------------------------------
#define GS_STAGE   35840
#define GS_BOFF    18432
#define GEMM_SMEM  107520

template<int NCOLS, bool HALF_OUT>
__global__ __launch_bounds__(256) void gemm_kernel(
    const half* __restrict__ A, const half* __restrict__ B,
    const float* __restrict__ bias, void* __restrict__ Cout)
{
    extern __shared__ unsigned char smem[];

    const int tid  = threadIdx.x;
    const int warp = tid >> 5, lane = tid & 31;
    const int m0 = blockIdx.y * 128, n0 = blockIdx.x * 128;
    const int wr = warp >> 1, wc = warp & 1;

    wmma::fragment<wmma::accumulator, 16, 16, 16, float> acc[2][4];
#pragma unroll
    for (int i = 0; i < 2; i++)
#pragma unroll
        for (int j = 0; j < 4; j++) wmma::fill_fragment(acc[i][j], 0.0f);

    auto load_chunk = [&](int c, int s) {
        int k0 = c * 64;
        half* as = (half*)(smem + s * GS_STAGE);
        half* bs = (half*)(smem + s * GS_STAGE + GS_BOFF);
        // A: 128x64 halfs = 1024 x 16B
#pragma unroll
        for (int i = 0; i < 4; i++) {
            int o = tid + i * 256;
            int row = o >> 3, c8 = o & 7;
            cp16(as + row * 72 + c8 * 8,
                 A + (size_t)(m0 + row) * EMB + k0 + c8 * 8);
        }
        // B: 64x128 halfs = 1024 x 16B
#pragma unroll
        for (int i = 0; i < 4; i++) {
            int o = tid + i * 256;
            int row = o >> 4, c8 = o & 15;
            cp16(bs + row * 136 + c8 * 8,
                 B + (size_t)(k0 + row) * NCOLS + n0 + c8 * 8);
        }
        cp_commit();
    };

    load_chunk(0, 0);
    load_chunk(1, 1);

    const int KC = EMB / 64;  // 6
#pragma unroll 1
    for (int kc = 0; kc < KC; kc++) {
        if (kc < KC - 1) cp_wait<1>(); else cp_wait<0>();   // chunk kc complete
        __syncthreads();                                    // buffers consumed @ kc-1 free
        if (kc + 2 < KC) load_chunk(kc + 2, (kc + 2) % 3);  // overlaps compute kc
        const half* as = (const half*)(smem + (kc % 3) * GS_STAGE);
        const half* bs = (const half*)(smem + (kc % 3) * GS_STAGE + GS_BOFF);
#pragma unroll
        for (int kk = 0; kk < 64; kk += 16) {
            wmma::fragment<wmma::matrix_a, 16, 16, 16, half, wmma::row_major> af[2];
            wmma::fragment<wmma::matrix_b, 16, 16, 16, half, wmma::row_major> bf[4];
#pragma unroll
            for (int i = 0; i < 2; i++)
                wmma::load_matrix_sync(af[i], as + (wr * 32 + i * 16) * 72 + kk, 72);
#pragma unroll
            for (int j = 0; j < 4; j++)
                wmma::load_matrix_sync(bf[j], bs + kk * 136 + wc * 64 + j * 16, 136);
#pragma unroll
            for (int i = 0; i < 2; i++)
#pragma unroll
                for (int j = 0; j < 4; j++)
                    wmma::mma_sync(acc[i][j], af[i], bf[j], acc[i][j]);
        }
    }
    __syncthreads();   // all compute done before epilogue reuses smem

    // Epilogue: per-warp fp32 stage [32][68], vectorized bias+convert+store.
    float* st = (float*)(smem + warp * 8704);
#pragma unroll
    for (int i = 0; i < 2; i++)
#pragma unroll
        for (int j = 0; j < 4; j++)
            wmma::store_matrix_sync(st + (i * 16) * 68 + j * 16, acc[i][j], 68,
                                    wmma::mem_row_major);
    const int rowbase = m0 + wr * 32;
    const int colbase = n0 + wc * 64;
#pragma unroll
    for (int e = 0; e < 16; e++) {
        int ci = e * 32 + lane;
        int r = ci >> 4, c4 = (ci & 15) << 2;
        float4 v = *(const float4*)(st + r * 68 + c4);
        float4 b4 = *(const float4*)(bias + colbase + c4);
        v.x += b4.x; v.y += b4.y; v.z += b4.z; v.w += b4.w;
        if (HALF_OUT) {
            h4 o;
            o.a = __floats2half2_rn(v.x, v.y);
            o.b = __floats2half2_rn(v.z, v.w);
            *(h4*)((half*)Cout + (size_t)(rowbase + r) * NCOLS + colbase + c4) = o;
        } else {
            *(float4*)((float*)Cout + (size_t)(rowbase + r) * NCOLS + colbase + c4) = v;
        }
    }
}

// ---------------------------------------------------------------------------
// Attention: one CTA per (batch, 64-row q tile). 32-row K/V subtiles,
// double-buffered cp.async, ONE sync per subtile; fp32 softmax.
// smem: QS h[64][392] | KV h[2][32][392] | SS f32[64][256] | PS h[64][256]
// ---------------------------------------------------------------------------
#define SM_QS 0
#define SM_KV0 50176
#define SM_KV1 75264
#define SM_SS 100352
#define SM_PS 165888
#define SMEM_ATTN 198656

__global__ __launch_bounds__(256) void attn_kernel()
{
    extern __shared__ unsigned char smem[];
    half*  QS = (half*)(smem + SM_QS);
    half*  KV[2] = { (half*)(smem + SM_KV0), (half*)(smem + SM_KV1) };
    float* SS = (float*)(smem + SM_SS);
    half*  PS = (half*)(smem + SM_PS);

    const int tid  = threadIdx.x;
    const int warp = tid >> 5, lane = tid & 31;
    const int b  = blockIdx.x >> 2;
    const int qt = blockIdx.x & 3;
    const int t0 = qt * QT_ROWS;
    const int nst = qt + 1;
    const int NS = nst * 2;          // 32-row subtiles
    const int send = nst * 64;

    auto load_kv = [&](int sub, int buf, int qkv_off) {
        const half* base = g_qkv + (size_t)(b * SEQ + sub * 32) * EMB3 + qkv_off;
#pragma unroll
        for (int i = 0; i < 6; i++) {
            int o = tid + i * 256;
            int row = o / 48, c = o % 48;
            cp16(KV[buf] + row * 392 + c * 8, base + (size_t)row * EMB3 + c * 8);
        }
        cp_commit();
    };

    // Prefetch Q + K0 as one group
    {
        const half* qbase = g_qkv + (size_t)(b * SEQ + t0) * EMB3;
#pragma unroll
        for (int i = 0; i < 12; i++) {
            int o = tid + i * 256;
            int row = o / 48, c = o % 48;
            cp16(QS + row * 392 + c * 8, qbase + (size_t)row * EMB3 + c * 8);
        }
        load_kv(0, 0, EMB);   // commits Q+K0 together
    }

    // ---- S = Q K^T : one sync per subtile ----
    const int wrS = warp >> 1, wcS = warp & 1;   // 4 row blocks x 2 col blocks
#pragma unroll 1
    for (int ss = 0; ss < NS; ss++) {
        cp_wait<0>();                              // subtile ss resident
        __syncthreads();                           // prev consumers done
        if (ss + 1 < NS) load_kv(ss + 1, (ss + 1) & 1, EMB);   // overlaps compute
        const half* ks = KV[ss & 1];

        wmma::fragment<wmma::accumulator, 16, 16, 16, float> s0, s1;
        wmma::fill_fragment(s0, 0.0f);
        wmma::fill_fragment(s1, 0.0f);
#pragma unroll
        for (int k = 0; k < EMB; k += 32) {
            wmma::fragment<wmma::matrix_a, 16, 16, 16, half, wmma::row_major> a0, a1;
            wmma::fragment<wmma::matrix_b, 16, 16, 16, half, wmma::col_major> b0, b1;
            wmma::load_matrix_sync(a0, QS + (wrS * 16) * 392 + k, 392);
            wmma::load_matrix_sync(b0, ks + (wcS * 16) * 392 + k, 392);
            wmma::load_matrix_sync(a1, QS + (wrS * 16) * 392 + k + 16, 392);
            wmma::load_matrix_sync(b1, ks + (wcS * 16) * 392 + k + 16, 392);
            wmma::mma_sync(s0, a0, b0, s0);
            wmma::mma_sync(s1, a1, b1, s1);
        }
#pragma unroll
        for (int e = 0; e < s0.num_elements; e++) s0.x[e] += s1.x[e];
        wmma::store_matrix_sync(SS + (wrS * 16) * 256 + ss * 32 + wcS * 16, s0, 256,
                                wmma::mem_row_major);
    }
    __syncthreads();          // S stores visible to all warps; KV buffers free

    // Prefetch V0, overlapped with softmax
    load_kv(0, 0, 2 * EMB);

    // ---- softmax (fp32) ----
    {
        const float inv_sqrt = 0.05103103630798288f;   // 1/sqrt(384)
        for (int r = warp * 8; r < warp * 8 + 8; r++) {
            int tglob = t0 + r;
            float* srow = SS + r * 256;
            float mx = -1e30f;
            for (int c = lane; c < send; c += 32) {
                float v = srow[c] * inv_sqrt;
                if (c > tglob) v = -1e30f;
                srow[c] = v;
                mx = fmaxf(mx, v);
            }
#pragma unroll
            for (int o = 16; o > 0; o >>= 1)
                mx = fmaxf(mx, __shfl_xor_sync(0xffffffffu, mx, o));
            float sum = 0.f;
            for (int c = lane; c < send; c += 32) {
                float e = __expf(srow[c] - mx);
                srow[c] = e;
                sum += e;
            }
#pragma unroll
            for (int o = 16; o > 0; o >>= 1)
                sum += __shfl_xor_sync(0xffffffffu, sum, o);
            float rs = 1.0f / sum;
            for (int c = lane; c < send; c += 32)
                PS[r * 256 + c] = __float2half_rn(srow[c] * rs);
        }
    }

    // ---- O = P @ V : one sync per subtile ----
    {
        const int wr = warp >> 1, wc = warp & 1;   // 4 x 16 rows, 2 x 192 cols
        wmma::fragment<wmma::accumulator, 16, 16, 16, float> o[12];
#pragma unroll
        for (int j = 0; j < 12; j++) wmma::fill_fragment(o[j], 0.0f);

#pragma unroll 1
        for (int sv = 0; sv < NS; sv++) {
            cp_wait<0>();                          // V subtile sv resident
            __syncthreads();                       // softmax/PS visible; prev V consumed
            if (sv + 1 < NS) load_kv(sv + 1, (sv + 1) & 1, 2 * EMB);
            const half* vs = KV[sv & 1];
#pragma unroll
            for (int kk = 0; kk < 2; kk++) {
                wmma::fragment<wmma::matrix_a, 16, 16, 16, half, wmma::row_major> af;
                wmma::load_matrix_sync(af, PS + (wr * 16) * 256 + sv * 32 + kk * 16, 256);
#pragma unroll
                for (int j = 0; j < 12; j++) {
                    wmma::fragment<wmma::matrix_b, 16, 16, 16, half, wmma::row_major> bf;
                    wmma::load_matrix_sync(bf, vs + (kk * 16) * 392 + wc * 192 + j * 16, 392);
                    wmma::mma_sync(o[j], af, bf, o[j]);
                }
            }
        }
        __syncthreads();   // all V reads done before OS overwrites QS/KV region

        // stage O fp32 in smem (reuse QS+KV region: 64x384 f32 = 96KB)
        float* OS = (float*)smem;
#pragma unroll
        for (int j = 0; j < 12; j++)
            wmma::store_matrix_sync(OS + (wr * 16) * 384 + wc * 192 + j * 16, o[j],
                                    384, wmma::mem_row_major);
        __syncthreads();
        half* obase = g_att + (size_t)(b * SEQ + t0) * EMB;
#pragma unroll
        for (int i = 0; i < 24; i++) {
            int oi = tid + i * 256;
            int row = oi / 96, c4 = (oi % 96) * 4;
            float4 v = *(const float4*)(OS + row * 384 + c4);
            h4 h;
            h.a = __floats2half2_rn(v.x, v.y);
            h.b = __floats2half2_rn(v.z, v.w);
            *(h4*)(obase + (size_t)row * EMB + c4) = h;
        }
    }
}

// ---------------------------------------------------------------------------
extern "C" void kernel_launch(void* const* d_in, const int* in_sizes, int n_in,
                              void* d_out, int out_size)
{
    const float* x     = (const float*)d_in[0];
    const float* Wqkv  = (const float*)d_in[1];
    const float* bqkv  = (const float*)d_in[2];
    const float* Wproj = (const float*)d_in[3];
    const float* bproj = (const float*)d_in[4];
    float* out = (float*)d_out;

    half *xh, *wqkvh, *wprojh, *qkv_ptr, *att_ptr;
    cudaGetSymbolAddress((void**)&xh, g_xh);
    cudaGetSymbolAddress((void**)&wqkvh, g_wqkv);
    cudaGetSymbolAddress((void**)&wprojh, g_wproj);
    cudaGetSymbolAddress((void**)&qkv_ptr, g_qkv);
    cudaGetSymbolAddress((void**)&att_ptr, g_att);

    cudaFuncSetAttribute(attn_kernel, cudaFuncAttributeMaxDynamicSharedMemorySize,
                         SMEM_ATTN);
    cudaFuncSetAttribute(gemm_kernel<EMB3, true>,
                         cudaFuncAttributeMaxDynamicSharedMemorySize, GEMM_SMEM);
    cudaFuncSetAttribute(gemm_kernel<EMB, false>,
                         cudaFuncAttributeMaxDynamicSharedMemorySize, GEMM_SMEM);

    // fp32 -> fp16 conversions
    {
        int n4x = MTOT * EMB / 4;                // 12582912
        f2h_kernel<<<(n4x + 255) / 256, 256>>>(x, xh, n4x);
        int n4q = EMB * EMB3 / 4;                // 110592
        f2h_kernel<<<(n4q + 255) / 256, 256>>>(Wqkv, wqkvh, n4q);
        int n4p = EMB * EMB / 4;                 // 36864
        f2h_kernel<<<(n4p + 255) / 256, 256>>>(Wproj, wprojh, n4p);
    }

    gemm_kernel<EMB3, true><<<dim3(EMB3 / 128, MTOT / 128), 256, GEMM_SMEM>>>(
        xh, wqkvh, bqkv, qkv_ptr);
    attn_kernel<<<BATCH * (SEQ / QT_ROWS), 256, SMEM_ATTN>>>();
    gemm_kernel<EMB, false><<<dim3(EMB / 128, MTOT / 128), 256, GEMM_SMEM>>>(
        att_ptr, wprojh, bproj, out);
}

// round 12
// speedup vs baseline: 2.5430x; 1.1136x over previous
#include <cuda_runtime.h>
#include <cuda_fp16.h>
#include <math_constants.h>
#include <mma.h>

using namespace nvcuda;

#define BATCH 512
#define SEQ   256
#define EMB   384
#define EMB3  1152
#define MTOT  (BATCH * SEQ)        // 131072

// Scratch (__device__ globals — allocation-free)
__device__ __align__(16) half g_xh [(size_t)MTOT * EMB];    // x in fp16
__device__ __align__(16) half g_wqkv[(size_t)EMB * EMB3];   // W_qkv fp16
__device__ __align__(16) half g_wproj[(size_t)EMB * EMB];   // W_proj fp16
__device__ __align__(16) half g_qkv[(size_t)MTOT * EMB3];   // q|k|v fp16
__device__ __align__(16) half g_att[(size_t)MTOT * EMB];    // attention out fp16

// ---------------------------------------------------------------------------
// cp.async helpers
// ---------------------------------------------------------------------------
__device__ __forceinline__ void cp16(void* smem, const void* gmem) {
    unsigned s = (unsigned)__cvta_generic_to_shared(smem);
    asm volatile("cp.async.cg.shared.global [%0], [%1], 16;\n" :: "r"(s), "l"(gmem));
}
__device__ __forceinline__ void cp_commit() {
    asm volatile("cp.async.commit_group;\n");
}
template<int N> __device__ __forceinline__ void cp_wait() {
    asm volatile("cp.async.wait_group %0;\n" :: "n"(N));
}

// ---------------------------------------------------------------------------
// fp32 -> fp16 conversion (vectorized)
// ---------------------------------------------------------------------------
struct h4 { half2 a, b; };
__global__ __launch_bounds__(256) void f2h_kernel(const float* __restrict__ src,
                                                  half* __restrict__ dst, int n4) {
    int i = blockIdx.x * 256 + threadIdx.x;
    if (i < n4) {
        float4 v = ((const float4*)src)[i];
        h4 o;
        o.a = __floats2half2_rn(v.x, v.y);
        o.b = __floats2half2_rn(v.z, v.w);
        ((h4*)dst)[i] = o;
    }
}

// ---------------------------------------------------------------------------
// Pipelined GEMM (unchanged from R8 validated): 3-stage cp.async,
// BM=128 BN=128 BK=64, 8 warps x (32x64), one sync per K-chunk.
// ---------------------------------------------------------------------------
#define GS_STAGE   35840
#define GS_BOFF    18432
#define GEMM_SMEM  107520

template<int NCOLS, bool HALF_OUT>
__global__ __launch_bounds__(256) void gemm_kernel(
    const half* __restrict__ A, const half* __restrict__ B,
    const float* __restrict__ bias, void* __restrict__ Cout)
{
    extern __shared__ unsigned char smem[];

    const int tid  = threadIdx.x;
    const int warp = tid >> 5, lane = tid & 31;
    const int m0 = blockIdx.y * 128, n0 = blockIdx.x * 128;
    const int wr = warp >> 1, wc = warp & 1;

    wmma::fragment<wmma::accumulator, 16, 16, 16, float> acc[2][4];
#pragma unroll
    for (int i = 0; i < 2; i++)
#pragma unroll
        for (int j = 0; j < 4; j++) wmma::fill_fragment(acc[i][j], 0.0f);

    auto load_chunk = [&](int c, int s) {
        int k0 = c * 64;
        half* as = (half*)(smem + s * GS_STAGE);
        half* bs = (half*)(smem + s * GS_STAGE + GS_BOFF);
#pragma unroll
        for (int i = 0; i < 4; i++) {
            int o = tid + i * 256;
            int row = o >> 3, c8 = o & 7;
            cp16(as + row * 72 + c8 * 8,
                 A + (size_t)(m0 + row) * EMB + k0 + c8 * 8);
        }
#pragma unroll
        for (int i = 0; i < 4; i++) {
            int o = tid + i * 256;
            int row = o >> 4, c8 = o & 15;
            cp16(bs + row * 136 + c8 * 8,
                 B + (size_t)(k0 + row) * NCOLS + n0 + c8 * 8);
        }
        cp_commit();
    };

    load_chunk(0, 0);
    load_chunk(1, 1);

    const int KC = EMB / 64;  // 6
#pragma unroll 1
    for (int kc = 0; kc < KC; kc++) {
        if (kc < KC - 1) cp_wait<1>(); else cp_wait<0>();
        __syncthreads();
        if (kc + 2 < KC) load_chunk(kc + 2, (kc + 2) % 3);
        const half* as = (const half*)(smem + (kc % 3) * GS_STAGE);
        const half* bs = (const half*)(smem + (kc % 3) * GS_STAGE + GS_BOFF);
#pragma unroll
        for (int kk = 0; kk < 64; kk += 16) {
            wmma::fragment<wmma::matrix_a, 16, 16, 16, half, wmma::row_major> af[2];
            wmma::fragment<wmma::matrix_b, 16, 16, 16, half, wmma::row_major> bf[4];
#pragma unroll
            for (int i = 0; i < 2; i++)
                wmma::load_matrix_sync(af[i], as + (wr * 32 + i * 16) * 72 + kk, 72);
#pragma unroll
            for (int j = 0; j < 4; j++)
                wmma::load_matrix_sync(bf[j], bs + kk * 136 + wc * 64 + j * 16, 136);
#pragma unroll
            for (int i = 0; i < 2; i++)
#pragma unroll
                for (int j = 0; j < 4; j++)
                    wmma::mma_sync(acc[i][j], af[i], bf[j], acc[i][j]);
        }
    }
    __syncthreads();

    float* st = (float*)(smem + warp * 8704);
#pragma unroll
    for (int i = 0; i < 2; i++)
#pragma unroll
        for (int j = 0; j < 4; j++)
            wmma::store_matrix_sync(st + (i * 16) * 68 + j * 16, acc[i][j], 68,
                                    wmma::mem_row_major);
    const int rowbase = m0 + wr * 32;
    const int colbase = n0 + wc * 64;
#pragma unroll
    for (int e = 0; e < 16; e++) {
        int ci = e * 32 + lane;
        int r = ci >> 4, c4 = (ci & 15) << 2;
        float4 v = *(const float4*)(st + r * 68 + c4);
        float4 b4 = *(const float4*)(bias + colbase + c4);
        v.x += b4.x; v.y += b4.y; v.z += b4.z; v.w += b4.w;
        if (HALF_OUT) {
            h4 o;
            o.a = __floats2half2_rn(v.x, v.y);
            o.b = __floats2half2_rn(v.z, v.w);
            *(h4*)((half*)Cout + (size_t)(rowbase + r) * NCOLS + colbase + c4) = o;
        } else {
            *(float4*)((float*)Cout + (size_t)(rowbase + r) * NCOLS + colbase + c4) = v;
        }
    }
}

// ---------------------------------------------------------------------------
// Attention v2: QT=32 q-rows, 128 threads (4 warps), 3 CTAs/SM.
// S stored as fp16 (scale+mask fused during scratch conversion); in-place
// softmax; single 32-key KV buffer (cross-CTA overlap hides load latency).
// smem: QS h[32][392] | KV h[32][392] | SSh h[32][264] | SC f32[4][256]
// ---------------------------------------------------------------------------
#define AQT   32
#define A_QS  0
#define A_KV  25088
#define A_SS  50176
#define A_SC  67072
#define SMEM_ATTN 71168

__global__ __launch_bounds__(128, 3) void attn_kernel()
{
    extern __shared__ unsigned char smem[];
    half* QS  = (half*)(smem + A_QS);    // ld 392
    half* KV  = (half*)(smem + A_KV);    // ld 392
    half* SSh = (half*)(smem + A_SS);    // ld 264 (S, then P in place)

    const int tid  = threadIdx.x;
    const int warp = tid >> 5, lane = tid & 31;
    const int b  = blockIdx.x >> 3;
    const int qt = blockIdx.x & 7;
    const int t0 = qt * AQT;
    const int nst = qt + 1;              // 32-key subtiles
    const int send = nst * 32;
    float* SC = (float*)(smem + A_SC) + warp * 256;   // per-warp 16x16 stage

    auto load_kv = [&](int sub, int off) {
        const half* base = g_qkv + (size_t)(b * SEQ + sub * 32) * EMB3 + off;
#pragma unroll
        for (int i = 0; i < 12; i++) {
            int o = tid + i * 128;
            int row = o / 48, c = o % 48;
            cp16(KV + row * 392 + c * 8, base + (size_t)row * EMB3 + c * 8);
        }
        cp_commit();
    };

    // Prefetch Q + K0 in one group
    {
        const half* qb = g_qkv + (size_t)(b * SEQ + t0) * EMB3;
#pragma unroll
        for (int i = 0; i < 12; i++) {
            int o = tid + i * 128;
            int row = o / 48, c = o % 48;
            cp16(QS + row * 392 + c * 8, qb + (size_t)row * EMB3 + c * 8);
        }
        load_kv(0, EMB);
    }

    const int wr = warp >> 1, wc = warp & 1;   // 2x16 rows, 2x16 cols
    const float inv_sqrt = 0.05103103630798288f;   // 1/sqrt(384)

    // ---- S = Q K^T (scale + causal mask fused into half conversion) ----
#pragma unroll 1
    for (int ss = 0; ss < nst; ss++) {
        cp_wait<0>();
        __syncthreads();                 // K_ss resident; prior phase done

        wmma::fragment<wmma::accumulator, 16, 16, 16, float> s0, s1;
        wmma::fill_fragment(s0, 0.0f);
        wmma::fill_fragment(s1, 0.0f);
#pragma unroll
        for (int k = 0; k < EMB; k += 32) {
            wmma::fragment<wmma::matrix_a, 16, 16, 16, half, wmma::row_major> a0, a1;
            wmma::fragment<wmma::matrix_b, 16, 16, 16, half, wmma::col_major> b0, b1;
            wmma::load_matrix_sync(a0, QS + (wr * 16) * 392 + k, 392);
            wmma::load_matrix_sync(b0, KV + (wc * 16) * 392 + k, 392);
            wmma::load_matrix_sync(a1, QS + (wr * 16) * 392 + k + 16, 392);
            wmma::load_matrix_sync(b1, KV + (wc * 16) * 392 + k + 16, 392);
            wmma::mma_sync(s0, a0, b0, s0);
            wmma::mma_sync(s1, a1, b1, s1);
        }
#pragma unroll
        for (int e = 0; e < s0.num_elements; e++) s0.x[e] += s1.x[e];

        wmma::store_matrix_sync(SC, s0, 16, wmma::mem_row_major);
        __syncwarp();
#pragma unroll
        for (int e = 0; e < 8; e++) {
            int idx = lane * 8 + e;
            int r = idx >> 4, c = idx & 15;
            int grow = wr * 16 + r;              // q row within tile
            int gcol = ss * 32 + wc * 16 + c;    // key index
            float v = SC[r * 16 + c] * inv_sqrt;
            SSh[grow * 264 + gcol] =
                (gcol > t0 + grow) ? __float2half(-CUDART_INF_F) : __float2half_rn(v);
        }
        __syncthreads();                 // KV consumed by all; S_ss visible
        if (ss + 1 < nst) load_kv(ss + 1, EMB);
    }

    // Prefetch V0 overlapped with softmax
    load_kv(0, 2 * EMB);

    // ---- softmax (fp32 math on half logits), in place ----
#pragma unroll 1
    for (int r = warp * 8; r < warp * 8 + 8; r++) {
        half* srow = SSh + r * 264;
        float vals[8];
        float mx = -1e30f;
        int cnt = 0;
        for (int c = lane; c < send; c += 32) {
            float v = __half2float(srow[c]);
            vals[cnt++] = v;
            mx = fmaxf(mx, v);
        }
#pragma unroll
        for (int o = 16; o > 0; o >>= 1)
            mx = fmaxf(mx, __shfl_xor_sync(0xffffffffu, mx, o));
        float sum = 0.f;
#pragma unroll
        for (int i = 0; i < 8; i++) {
            if (i < cnt) {
                float e = __expf(vals[i] - mx);
                vals[i] = e;
                sum += e;
            }
        }
#pragma unroll
        for (int o = 16; o > 0; o >>= 1)
            sum += __shfl_xor_sync(0xffffffffu, sum, o);
        float rs = 1.0f / sum;
        cnt = 0;
        for (int c = lane; c < send; c += 32)
            srow[c] = __float2half_rn(vals[cnt++] * rs);
    }

    // ---- O = P @ V ----
    {
        wmma::fragment<wmma::accumulator, 16, 16, 16, float> o[12];
#pragma unroll
        for (int j = 0; j < 12; j++) wmma::fill_fragment(o[j], 0.0f);

#pragma unroll 1
        for (int sv = 0; sv < nst; sv++) {
            cp_wait<0>();
            __syncthreads();             // V resident; P visible (1st iter)
#pragma unroll
            for (int kk = 0; kk < 32; kk += 16) {
                wmma::fragment<wmma::matrix_a, 16, 16, 16, half, wmma::row_major> af;
                wmma::load_matrix_sync(af, SSh + (wr * 16) * 264 + sv * 32 + kk, 264);
#pragma unroll
                for (int j = 0; j < 12; j++) {
                    wmma::fragment<wmma::matrix_b, 16, 16, 16, half, wmma::row_major> bf;
                    wmma::load_matrix_sync(bf, KV + kk * 392 + wc * 192 + j * 16, 392);
                    wmma::mma_sync(o[j], af, bf, o[j]);
                }
            }
            __syncthreads();             // V consumed before next load / OS reuse
            if (sv + 1 < nst) load_kv(sv + 1, 2 * EMB);
        }

        // stage O fp32 (reuse QS+KV region: 32x384 f32 = 49152 B)
        float* OS = (float*)smem;
#pragma unroll
        for (int j = 0; j < 12; j++)
            wmma::store_matrix_sync(OS + (wr * 16) * 384 + wc * 192 + j * 16, o[j],
                                    384, wmma::mem_row_major);
        __syncthreads();
        half* obase = g_att + (size_t)(b * SEQ + t0) * EMB;
#pragma unroll
        for (int i = 0; i < 24; i++) {
            int oi = tid + i * 128;
            int row = oi / 96, c4 = (oi % 96) * 4;
            float4 v = *(const float4*)(OS + row * 384 + c4);
            h4 h;
            h.a = __floats2half2_rn(v.x, v.y);
            h.b = __floats2half2_rn(v.z, v.w);
            *(h4*)(obase + (size_t)row * EMB + c4) = h;
        }
    }
}

// ---------------------------------------------------------------------------
extern "C" void kernel_launch(void* const* d_in, const int* in_sizes, int n_in,
                              void* d_out, int out_size)
{
    const float* x     = (const float*)d_in[0];
    const float* Wqkv  = (const float*)d_in[1];
    const float* bqkv  = (const float*)d_in[2];
    const float* Wproj = (const float*)d_in[3];
    const float* bproj = (const float*)d_in[4];
    float* out = (float*)d_out;

    half *xh, *wqkvh, *wprojh, *qkv_ptr, *att_ptr;
    cudaGetSymbolAddress((void**)&xh, g_xh);
    cudaGetSymbolAddress((void**)&wqkvh, g_wqkv);
    cudaGetSymbolAddress((void**)&wprojh, g_wproj);
    cudaGetSymbolAddress((void**)&qkv_ptr, g_qkv);
    cudaGetSymbolAddress((void**)&att_ptr, g_att);

    cudaFuncSetAttribute(attn_kernel, cudaFuncAttributeMaxDynamicSharedMemorySize,
                         SMEM_ATTN);
    cudaFuncSetAttribute(gemm_kernel<EMB3, true>,
                         cudaFuncAttributeMaxDynamicSharedMemorySize, GEMM_SMEM);
    cudaFuncSetAttribute(gemm_kernel<EMB, false>,
                         cudaFuncAttributeMaxDynamicSharedMemorySize, GEMM_SMEM);

    // fp32 -> fp16 conversions
    {
        int n4x = MTOT * EMB / 4;
        f2h_kernel<<<(n4x + 255) / 256, 256>>>(x, xh, n4x);
        int n4q = EMB * EMB3 / 4;
        f2h_kernel<<<(n4q + 255) / 256, 256>>>(Wqkv, wqkvh, n4q);
        int n4p = EMB * EMB / 4;
        f2h_kernel<<<(n4p + 255) / 256, 256>>>(Wproj, wprojh, n4p);
    }

    gemm_kernel<EMB3, true><<<dim3(EMB3 / 128, MTOT / 128), 256, GEMM_SMEM>>>(
        xh, wqkvh, bqkv, qkv_ptr);
    attn_kernel<<<BATCH * (SEQ / AQT), 128, SMEM_ATTN>>>();
    gemm_kernel<EMB, false><<<dim3(EMB / 128, MTOT / 128), 256, GEMM_SMEM>>>(
        att_ptr, wprojh, bproj, out);
}

// round 15
// speedup vs baseline: 2.6739x; 1.0514x over previous
#include <cuda_runtime.h>
#include <cuda_fp16.h>
#include <math_constants.h>
#include <mma.h>

using namespace nvcuda;

#define BATCH 512
#define SEQ   256
#define EMB   384
#define EMB3  1152
#define MTOT  (BATCH * SEQ)        // 131072

// Scratch (__device__ globals — allocation-free)
__device__ __align__(16) half g_xh [(size_t)MTOT * EMB];    // x in fp16
__device__ __align__(16) half g_wqkv[(size_t)EMB * EMB3];   // W_qkv fp16
__device__ __align__(16) half g_wproj[(size_t)EMB * EMB];   // W_proj fp16
__device__ __align__(16) half g_qkv[(size_t)MTOT * EMB3];   // q|k|v fp16
__device__ __align__(16) half g_att[(size_t)MTOT * EMB];    // attention out fp16

// ---------------------------------------------------------------------------
// cp.async helpers
// ---------------------------------------------------------------------------
__device__ __forceinline__ void cp16(void* smem, const void* gmem) {
    unsigned s = (unsigned)__cvta_generic_to_shared(smem);
    asm volatile("cp.async.cg.shared.global [%0], [%1], 16;\n" :: "r"(s), "l"(gmem));
}
__device__ __forceinline__ void cp_commit() {
    asm volatile("cp.async.commit_group;\n");
}
template<int N> __device__ __forceinline__ void cp_wait() {
    asm volatile("cp.async.wait_group %0;\n" :: "n"(N));
}

// ---------------------------------------------------------------------------
// fp32 -> fp16 conversion (vectorized)
// ---------------------------------------------------------------------------
struct h4 { half2 a, b; };
__global__ __launch_bounds__(256) void f2h_kernel(const float* __restrict__ src,
                                                  half* __restrict__ dst, int n4) {
    int i = blockIdx.x * 256 + threadIdx.x;
    if (i < n4) {
        float4 v = ((const float4*)src)[i];
        h4 o;
        o.a = __floats2half2_rn(v.x, v.y);
        o.b = __floats2half2_rn(v.z, v.w);
        ((h4*)dst)[i] = o;
    }
}

// ---------------------------------------------------------------------------
// Pipelined GEMM v2: BM=128 BN=128 BK=64, 3-stage cp.async,
// 4 warps x (64x64) — 2.0 MMA per fragment load (was 1.33 with 8x(32x64)).
// 128 threads; 2 CTAs/SM (smem-bound).
// smem per stage: As 128x72 h (18432B) + Bs 64x136 h (17408B) = 35840B
// 3 stages = 107520B; epilogue: per-warp fp32 stage 64x68 (17408B x4).
// ---------------------------------------------------------------------------
#define GS_STAGE   35840
#define GS_BOFF    18432
#define GEMM_SMEM  107520

template<int NCOLS, bool HALF_OUT>
__global__ __launch_bounds__(128) void gemm_kernel(
    const half* __restrict__ A, const half* __restrict__ B,
    const float* __restrict__ bias, void* __restrict__ Cout)
{
    extern __shared__ unsigned char smem[];

    const int tid  = threadIdx.x;
    const int warp = tid >> 5, lane = tid & 31;
    const int m0 = blockIdx.y * 128, n0 = blockIdx.x * 128;
    const int wr = warp >> 1, wc = warp & 1;   // 2x2 warps of 64x64

    wmma::fragment<wmma::accumulator, 16, 16, 16, float> acc[4][4];
#pragma unroll
    for (int i = 0; i < 4; i++)
#pragma unroll
        for (int j = 0; j < 4; j++) wmma::fill_fragment(acc[i][j], 0.0f);

    auto load_chunk = [&](int c, int s) {
        int k0 = c * 64;
        half* as = (half*)(smem + s * GS_STAGE);
        half* bs = (half*)(smem + s * GS_STAGE + GS_BOFF);
        // A: 128 rows x 64 halfs = 1024 x 16B, 8 per thread
#pragma unroll
        for (int i = 0; i < 8; i++) {
            int o = tid + i * 128;
            int row = o >> 3, c8 = o & 7;
            cp16(as + row * 72 + c8 * 8,
                 A + (size_t)(m0 + row) * EMB + k0 + c8 * 8);
        }
        // B: 64 rows x 128 halfs = 1024 x 16B, 8 per thread
#pragma unroll
        for (int i = 0; i < 8; i++) {
            int o = tid + i * 128;
            int row = o >> 4, c8 = o & 15;
            cp16(bs + row * 136 + c8 * 8,
                 B + (size_t)(k0 + row) * NCOLS + n0 + c8 * 8);
        }
        cp_commit();
    };

    load_chunk(0, 0);
    load_chunk(1, 1);

    const int KC = EMB / 64;  // 6
#pragma unroll 1
    for (int kc = 0; kc < KC; kc++) {
        if (kc < KC - 1) cp_wait<1>(); else cp_wait<0>();
        __syncthreads();
        if (kc + 2 < KC) load_chunk(kc + 2, (kc + 2) % 3);
        const half* as = (const half*)(smem + (kc % 3) * GS_STAGE);
        const half* bs = (const half*)(smem + (kc % 3) * GS_STAGE + GS_BOFF);
#pragma unroll
        for (int kk = 0; kk < 64; kk += 16) {
            wmma::fragment<wmma::matrix_a, 16, 16, 16, half, wmma::row_major> af[4];
            wmma::fragment<wmma::matrix_b, 16, 16, 16, half, wmma::row_major> bf[4];
#pragma unroll
            for (int i = 0; i < 4; i++)
                wmma::load_matrix_sync(af[i], as + (wr * 64 + i * 16) * 72 + kk, 72);
#pragma unroll
            for (int j = 0; j < 4; j++)
                wmma::load_matrix_sync(bf[j], bs + kk * 136 + wc * 64 + j * 16, 136);
#pragma unroll
            for (int i = 0; i < 4; i++)
#pragma unroll
                for (int j = 0; j < 4; j++)
                    wmma::mma_sync(acc[i][j], af[i], bf[j], acc[i][j]);
        }
    }
    __syncthreads();   // all compute done before epilogue reuses smem

    // Epilogue: per-warp fp32 stage [64][68] (17408 B each, 4 warps = 69632 B)
    float* st = (float*)(smem + warp * 17408);
#pragma unroll
    for (int i = 0; i < 4; i++)
#pragma unroll
        for (int j = 0; j < 4; j++)
            wmma::store_matrix_sync(st + (i * 16) * 68 + j * 16, acc[i][j], 68,
                                    wmma::mem_row_major);
    const int rowbase = m0 + wr * 64;
    const int colbase = n0 + wc * 64;
#pragma unroll
    for (int e = 0; e < 32; e++) {
        int ci = e * 32 + lane;            // 1024 float4s per warp
        int r = ci >> 4, c4 = (ci & 15) << 2;
        float4 v = *(const float4*)(st + r * 68 + c4);
        float4 b4 = *(const float4*)(bias + colbase + c4);
        v.x += b4.x; v.y += b4.y; v.z += b4.z; v.w += b4.w;
        if (HALF_OUT) {
            h4 o;
            o.a = __floats2half2_rn(v.x, v.y);
            o.b = __floats2half2_rn(v.z, v.w);
            *(h4*)((half*)Cout + (size_t)(rowbase + r) * NCOLS + colbase + c4) = o;
        } else {
            *(float4*)((float*)Cout + (size_t)(rowbase + r) * NCOLS + colbase + c4) = v;
        }
    }
}

// ---------------------------------------------------------------------------
// Attention v2 (unchanged from R12 validated): QT=32 q-rows, 128 threads,
// 3 CTAs/SM; fp16 logits with fused scale+mask; in-place softmax.
// ---------------------------------------------------------------------------
#define AQT   32
#define A_QS  0
#define A_KV  25088
#define A_SS  50176
#define A_SC  67072
#define SMEM_ATTN 71168

__global__ __launch_bounds__(128, 3) void attn_kernel()
{
    extern __shared__ unsigned char smem[];
    half* QS  = (half*)(smem + A_QS);    // ld 392
    half* KV  = (half*)(smem + A_KV);    // ld 392
    half* SSh = (half*)(smem + A_SS);    // ld 264 (S, then P in place)

    const int tid  = threadIdx.x;
    const int warp = tid >> 5, lane = tid & 31;
    const int b  = blockIdx.x >> 3;
    const int qt = blockIdx.x & 7;
    const int t0 = qt * AQT;
    const int nst = qt + 1;              // 32-key subtiles
    const int send = nst * 32;
    float* SC = (float*)(smem + A_SC) + warp * 256;   // per-warp 16x16 stage

    auto load_kv = [&](int sub, int off) {
        const half* base = g_qkv + (size_t)(b * SEQ + sub * 32) * EMB3 + off;
#pragma unroll
        for (int i = 0; i < 12; i++) {
            int o = tid + i * 128;
            int row = o / 48, c = o % 48;
            cp16(KV + row * 392 + c * 8, base + (size_t)row * EMB3 + c * 8);
        }
        cp_commit();
    };

    // Prefetch Q + K0 in one group
    {
        const half* qb = g_qkv + (size_t)(b * SEQ + t0) * EMB3;
#pragma unroll
        for (int i = 0; i < 12; i++) {
            int o = tid + i * 128;
            int row = o / 48, c = o % 48;
            cp16(QS + row * 392 + c * 8, qb + (size_t)row * EMB3 + c * 8);
        }
        load_kv(0, EMB);
    }

    const int wr = warp >> 1, wc = warp & 1;   // 2x16 rows, 2x16 cols
    const float inv_sqrt = 0.05103103630798288f;   // 1/sqrt(384)

    // ---- S = Q K^T (scale + causal mask fused into half conversion) ----
#pragma unroll 1
    for (int ss = 0; ss < nst; ss++) {
        cp_wait<0>();
        __syncthreads();                 // K_ss resident; prior phase done

        wmma::fragment<wmma::accumulator, 16, 16, 16, float> s0, s1;
        wmma::fill_fragment(s0, 0.0f);
        wmma::fill_fragment(s1, 0.0f);
#pragma unroll
        for (int k = 0; k < EMB; k += 32) {
            wmma::fragment<wmma::matrix_a, 16, 16, 16, half, wmma::row_major> a0, a1;
            wmma::fragment<wmma::matrix_b, 16, 16, 16, half, wmma::col_major> b0, b1;
            wmma::load_matrix_sync(a0, QS + (wr * 16) * 392 + k, 392);
            wmma::load_matrix_sync(b0, KV + (wc * 16) * 392 + k, 392);
            wmma::load_matrix_sync(a1, QS + (wr * 16) * 392 + k + 16, 392);
            wmma::load_matrix_sync(b1, KV + (wc * 16) * 392 + k + 16, 392);
            wmma::mma_sync(s0, a0, b0, s0);
            wmma::mma_sync(s1, a1, b1, s1);
        }
#pragma unroll
        for (int e = 0; e < s0.num_elements; e++) s0.x[e] += s1.x[e];

        wmma::store_matrix_sync(SC, s0, 16, wmma::mem_row_major);
        __syncwarp();
#pragma unroll
        for (int e = 0; e < 8; e++) {
            int idx = lane * 8 + e;
            int r = idx >> 4, c = idx & 15;
            int grow = wr * 16 + r;              // q row within tile
            int gcol = ss * 32 + wc * 16 + c;    // key index
            float v = SC[r * 16 + c] * inv_sqrt;
            SSh[grow * 264 + gcol] =
                (gcol > t0 + grow) ? __float2half(-CUDART_INF_F) : __float2half_rn(v);
        }
        __syncthreads();                 // KV consumed by all; S_ss visible
        if (ss + 1 < nst) load_kv(ss + 1, EMB);
    }

    // Prefetch V0 overlapped with softmax
    load_kv(0, 2 * EMB);

    // ---- softmax (fp32 math on half logits), in place ----
#pragma unroll 1
    for (int r = warp * 8; r < warp * 8 + 8; r++) {
        half* srow = SSh + r * 264;
        float vals[8];
        float mx = -1e30f;
        int cnt = 0;
        for (int c = lane; c < send; c += 32) {
            float v = __half2float(srow[c]);
            vals[cnt++] = v;
            mx = fmaxf(mx, v);
        }
#pragma unroll
        for (int o = 16; o > 0; o >>= 1)
            mx = fmaxf(mx, __shfl_xor_sync(0xffffffffu, mx, o));
        float sum = 0.f;
#pragma unroll
        for (int i = 0; i < 8; i++) {
            if (i < cnt) {
                float e = __expf(vals[i] - mx);
                vals[i] = e;
                sum += e;
            }
        }
#pragma unroll
        for (int o = 16; o > 0; o >>= 1)
            sum += __shfl_xor_sync(0xffffffffu, sum, o);
        float rs = 1.0f / sum;
        cnt = 0;
        for (int c = lane; c < send; c += 32)
            srow[c] = __float2half_rn(vals[cnt++] * rs);
    }

    // ---- O = P @ V ----
    {
        wmma::fragment<wmma::accumulator, 16, 16, 16, float> o[12];
#pragma unroll
        for (int j = 0; j < 12; j++) wmma::fill_fragment(o[j], 0.0f);

#pragma unroll 1
        for (int sv = 0; sv < nst; sv++) {
            cp_wait<0>();
            __syncthreads();             // V resident; P visible (1st iter)
#pragma unroll
            for (int kk = 0; kk < 32; kk += 16) {
                wmma::fragment<wmma::matrix_a, 16, 16, 16, half, wmma::row_major> af;
                wmma::load_matrix_sync(af, SSh + (wr * 16) * 264 + sv * 32 + kk, 264);
#pragma unroll
                for (int j = 0; j < 12; j++) {
                    wmma::fragment<wmma::matrix_b, 16, 16, 16, half, wmma::row_major> bf;
                    wmma::load_matrix_sync(bf, KV + kk * 392 + wc * 192 + j * 16, 392);
                    wmma::mma_sync(o[j], af, bf, o[j]);
                }
            }
            __syncthreads();             // V consumed before next load / OS reuse
            if (sv + 1 < nst) load_kv(sv + 1, 2 * EMB);
        }

        // stage O fp32 (reuse QS+KV region: 32x384 f32 = 49152 B)
        float* OS = (float*)smem;
#pragma unroll
        for (int j = 0; j < 12; j++)
            wmma::store_matrix_sync(OS + (wr * 16) * 384 + wc * 192 + j * 16, o[j],
                                    384, wmma::mem_row_major);
        __syncthreads();
        half* obase = g_att + (size_t)(b * SEQ + t0) * EMB;
#pragma unroll
        for (int i = 0; i < 24; i++) {
            int oi = tid + i * 128;
            int row = oi / 96, c4 = (oi % 96) * 4;
            float4 v = *(const float4*)(OS + row * 384 + c4);
            h4 h;
            h.a = __floats2half2_rn(v.x, v.y);
            h.b = __floats2half2_rn(v.z, v.w);
            *(h4*)(obase + (size_t)row * EMB + c4) = h;
        }
    }
}

// ---------------------------------------------------------------------------
extern "C" void kernel_launch(void* const* d_in, const int* in_sizes, int n_in,
                              void* d_out, int out_size)
{
    const float* x     = (const float*)d_in[0];
    const float* Wqkv  = (const float*)d_in[1];
    const float* bqkv  = (const float*)d_in[2];
    const float* Wproj = (const float*)d_in[3];
    const float* bproj = (const float*)d_in[4];
    float* out = (float*)d_out;

    half *xh, *wqkvh, *wprojh, *qkv_ptr, *att_ptr;
    cudaGetSymbolAddress((void**)&xh, g_xh);
    cudaGetSymbolAddress((void**)&wqkvh, g_wqkv);
    cudaGetSymbolAddress((void**)&wprojh, g_wproj);
    cudaGetSymbolAddress((void**)&qkv_ptr, g_qkv);
    cudaGetSymbolAddress((void**)&att_ptr, g_att);

    cudaFuncSetAttribute(attn_kernel, cudaFuncAttributeMaxDynamicSharedMemorySize,
                         SMEM_ATTN);
    cudaFuncSetAttribute(gemm_kernel<EMB3, true>,
                         cudaFuncAttributeMaxDynamicSharedMemorySize, GEMM_SMEM);
    cudaFuncSetAttribute(gemm_kernel<EMB, false>,
                         cudaFuncAttributeMaxDynamicSharedMemorySize, GEMM_SMEM);

    // fp32 -> fp16 conversions
    {
        int n4x = MTOT * EMB / 4;
        f2h_kernel<<<(n4x + 255) / 256, 256>>>(x, xh, n4x);
        int n4q = EMB * EMB3 / 4;
        f2h_kernel<<<(n4q + 255) / 256, 256>>>(Wqkv, wqkvh, n4q);
        int n4p = EMB * EMB / 4;
        f2h_kernel<<<(n4p + 255) / 256, 256>>>(Wproj, wprojh, n4p);
    }

    gemm_kernel<EMB3, true><<<dim3(EMB3 / 128, MTOT / 128), 128, GEMM_SMEM>>>(
        xh, wqkvh, bqkv, qkv_ptr);
    attn_kernel<<<BATCH * (SEQ / AQT), 128, SMEM_ATTN>>>();
    gemm_kernel<EMB, false><<<dim3(EMB / 128, MTOT / 128), 128, GEMM_SMEM>>>(
        att_ptr, wprojh, bproj, out);
}